// round 2
// baseline (speedup 1.0000x reference)
#include <cuda_runtime.h>
#include <cuda_bf16.h>

// ---------------------------------------------------------------------------
// UMTP propagation, v2.
//  - rows padded to 56 floats (224B = 7 aligned 32B sectors)
//  - spmm: warp per node, two 16-lane groups each gathering an independent
//    edge stream with 14 float4 lanes, x2 unroll -> 4 gathers in flight/warp
//  - parallel 3-phase prefix scan (was 166us single-block)
// ---------------------------------------------------------------------------

#define NMAX     100000
#define EMAX     1600000
#define DATTR    50
#define SPAD     56          // padded floats per row
#define S4       14          // float4 per row
#define NUM_ITER 30
#define WPB      8           // warps per block
#define SCANB    1024        // elements per scan block

__device__ int    g_deg[NMAX];
__device__ float  g_dinv[NMAX];
__device__ int    g_rowptr[NMAX + 1];
__device__ int    g_cursor[NMAX];
__device__ int2   g_csr[EMAX];
__device__ unsigned char g_known[NMAX];
__device__ int    g_bsum[128];
__device__ int    g_boff[128];
__device__ float4 g_mean4[S4];
__device__ float4 g_alpha4[S4];
__device__ float4 g_beta4[S4];
__device__ float4 g_colsum4[(NUM_ITER + 1) * S4];
__device__ float4 g_bufA[NMAX * S4];
__device__ float4 g_bufB[NMAX * S4];
__device__ float4 g_xk[NMAX * S4];      // x - mean, padded

// ---- 0) zero per-launch state (graph replays reuse device globals) ----
__global__ void zero_kernel(int n) {
    int i = blockIdx.x * blockDim.x + threadIdx.x;
    if (i < n) { g_deg[i] = 0; g_known[i] = 0; }
    float* mean = (float*)g_mean4;
    float* cs = (float*)g_colsum4;
    if (i < SPAD) mean[i] = 0.0f;
    if (i < (NUM_ITER + 1) * SPAD) cs[i] = 0.0f;
}

// ---- 1) out-degree histogram ----
__global__ void deg_kernel(const int* __restrict__ row, int e) {
    int j = blockIdx.x * blockDim.x + threadIdx.x;
    if (j < e) atomicAdd(&g_deg[row[j]], 1);
}

// ---- 2) dinv + alpha/beta (padded entries -> 1.0) ----
__global__ void dinv_alpha_kernel(const float* __restrict__ eta,
                                  const float* __restrict__ theta,
                                  int n, int d) {
    int i = blockIdx.x * blockDim.x + threadIdx.x;
    if (i < n) {
        int dg = g_deg[i];
        g_dinv[i] = (dg > 0) ? rsqrtf((float)dg) : 0.0f;
    }
    if (i < SPAD) {
        float* al = (float*)g_alpha4;
        float* be = (float*)g_beta4;
        if (i < d) {
            float nf = (float)n;
            float a = (nf - 1.0f) / (theta[i] * nf + (nf - 1.0f));
            al[i] = a;
            float inva = 1.0f / a;
            be[i] = inva / (inva + eta[i]);
        } else {
            al[i] = 1.0f; be[i] = 1.0f;
        }
    }
}

// ---- 3a) per-block degree sums ----
__global__ void scan_sum_kernel(int n) {
    __shared__ int ssum;
    if (threadIdx.x == 0) ssum = 0;
    __syncthreads();
    int i = blockIdx.x * SCANB + threadIdx.x;
    int v = (i < n) ? g_deg[i] : 0;
    #pragma unroll
    for (int off = 16; off > 0; off >>= 1)
        v += __shfl_down_sync(0xffffffffu, v, off);
    if ((threadIdx.x & 31) == 0) atomicAdd(&ssum, v);
    __syncthreads();
    if (threadIdx.x == 0) g_bsum[blockIdx.x] = ssum;
}

// ---- 3b) scan the block sums (single small block) ----
__global__ void scan_top_kernel(int nb, int n) {
    __shared__ int s[128];
    int t = threadIdx.x;
    int v = (t < nb) ? g_bsum[t] : 0;
    s[t] = v;
    __syncthreads();
    #pragma unroll
    for (int off = 1; off < 128; off <<= 1) {
        int tv = (t >= off) ? s[t - off] : 0;
        __syncthreads();
        s[t] += tv;
        __syncthreads();
    }
    if (t < nb) g_boff[t] = s[t] - v;   // exclusive
    if (t == nb - 1) g_rowptr[n] = s[t];
}

// ---- 3c) per-block exclusive scan + offset ----
__global__ void scan_write_kernel(int n) {
    __shared__ int s[SCANB];
    int tid = threadIdx.x;
    int i = blockIdx.x * SCANB + tid;
    int v = (i < n) ? g_deg[i] : 0;
    s[tid] = v;
    __syncthreads();
    #pragma unroll
    for (int off = 1; off < SCANB; off <<= 1) {
        int tv = (tid >= off) ? s[tid - off] : 0;
        __syncthreads();
        s[tid] += tv;
        __syncthreads();
    }
    if (i < n) {
        int excl = g_boff[blockIdx.x] + s[tid] - v;
        g_rowptr[i] = excl;
        g_cursor[i] = excl;
    }
}

// ---- 4) scatter edges into CSR ----
__global__ void scatter_kernel(const int* __restrict__ row,
                               const int* __restrict__ col, int e) {
    int j = blockIdx.x * blockDim.x + threadIdx.x;
    if (j < e) {
        int r = row[j], c = col[j];
        float w = g_dinv[r] * g_dinv[c];
        int pos = atomicAdd(&g_cursor[r], 1);
        g_csr[pos] = make_int2(c, __float_as_int(w));
    }
}

// ---- 5) known flags + mean sums over mask ----
__global__ void mask_mean_kernel(const float* __restrict__ x,
                                 const int* __restrict__ mask, int kcnt) {
    int lane = threadIdx.x & 31;
    int wid = threadIdx.x >> 5;
    int gw = blockIdx.x * (blockDim.x >> 5) + wid;
    int nw = gridDim.x * (blockDim.x >> 5);
    const float2* x2 = (const float2*)x;
    float ax = 0.0f, ay = 0.0f;
    for (int j = gw; j < kcnt; j += nw) {
        int i = mask[j];
        if (lane == 0) g_known[i] = 1;
        if (lane < 25) {
            float2 v = __ldg(&x2[i * 25 + lane]);
            ax += v.x; ay += v.y;
        }
    }
    __shared__ float sm[SPAD];
    if (threadIdx.x < SPAD) sm[threadIdx.x] = 0.0f;
    __syncthreads();
    if (lane < 25) {
        atomicAdd(&sm[2 * lane], ax);
        atomicAdd(&sm[2 * lane + 1], ay);
    }
    __syncthreads();
    if (threadIdx.x < DATTR) atomicAdd(&((float*)g_mean4)[threadIdx.x], sm[threadIdx.x]);
}

__global__ void mean_div_kernel(int kcnt) {
    if (threadIdx.x < DATTR) ((float*)g_mean4)[threadIdx.x] *= (1.0f / (float)kcnt);
}

// ---- 6) xk = x - mean (padded); buf0 = (known? x:0) - mean; colsum slot 0 ----
__global__ void __launch_bounds__(256) init_kernel(const float* __restrict__ x, int n) {
    int lane = threadIdx.x & 31;
    int i = (blockIdx.x * blockDim.x + threadIdx.x) >> 5;
    float vx = 0.0f, vy = 0.0f;
    if (i < n && lane < 28) {
        float2* xk2 = (float2*)g_xk;
        float2* b2 = (float2*)g_bufA;
        if (lane < 25) {
            const float2* x2 = (const float2*)x;
            float2 xv = __ldg(&x2[i * 25 + lane]);
            float m0 = ((float*)g_mean4)[2 * lane];
            float m1 = ((float*)g_mean4)[2 * lane + 1];
            float kx = xv.x - m0, ky = xv.y - m1;
            xk2[i * 28 + lane] = make_float2(kx, ky);
            if (g_known[i]) { vx = kx; vy = ky; }
            else            { vx = -m0; vy = -m1; }
            b2[i * 28 + lane] = make_float2(vx, vy);
        } else {
            xk2[i * 28 + lane] = make_float2(0.0f, 0.0f);
            b2[i * 28 + lane] = make_float2(0.0f, 0.0f);
        }
    }
    __shared__ float sm[SPAD];
    if (threadIdx.x < SPAD) sm[threadIdx.x] = 0.0f;
    __syncthreads();
    if (i < n && lane < 25) {
        atomicAdd(&sm[2 * lane], vx);
        atomicAdd(&sm[2 * lane + 1], vy);
    }
    __syncthreads();
    if (threadIdx.x < DATTR)
        atomicAdd(&((float*)g_colsum4)[threadIdx.x], sm[threadIdx.x]);
}

// ---- 7) propagation step: warp/node, 2 edge groups x 14 float4 lanes ----
__global__ void __launch_bounds__(256) spmm_kernel(
    const float4* __restrict__ src, float4* __restrict__ dst,
    float* __restrict__ dout,
    const float4* __restrict__ colsum_in, float* __restrict__ colsum_out,
    int n, float inv_n, int final_add_mean) {

    int lane = threadIdx.x & 31;
    int i = (blockIdx.x * blockDim.x + threadIdx.x) >> 5;
    int g = lane >> 4;          // edge group 0/1
    int sl = lane & 15;         // lane within group
    bool act = (sl < S4);
    bool valid = (i < n);
    float4 acc = make_float4(0.0f, 0.0f, 0.0f, 0.0f);
    float4 outv = make_float4(0.0f, 0.0f, 0.0f, 0.0f);

    if (valid) {
        int jb = g_rowptr[i], je = g_rowptr[i + 1];
        int j = jb + g;
        for (; j + 2 < je; j += 4) {
            int2 cw0 = __ldg(&g_csr[j]);
            int2 cw1 = __ldg(&g_csr[j + 2]);
            if (act) {
                float4 v0 = __ldg(&src[cw0.x * S4 + sl]);
                float4 v1 = __ldg(&src[cw1.x * S4 + sl]);
                float w0 = __int_as_float(cw0.y);
                float w1 = __int_as_float(cw1.y);
                acc.x = fmaf(w0, v0.x, acc.x); acc.y = fmaf(w0, v0.y, acc.y);
                acc.z = fmaf(w0, v0.z, acc.z); acc.w = fmaf(w0, v0.w, acc.w);
                acc.x = fmaf(w1, v1.x, acc.x); acc.y = fmaf(w1, v1.y, acc.y);
                acc.z = fmaf(w1, v1.z, acc.z); acc.w = fmaf(w1, v1.w, acc.w);
            }
        }
        if (j < je) {
            int2 cw = __ldg(&g_csr[j]);
            if (act) {
                float4 v = __ldg(&src[cw.x * S4 + sl]);
                float w = __int_as_float(cw.y);
                acc.x = fmaf(w, v.x, acc.x); acc.y = fmaf(w, v.y, acc.y);
                acc.z = fmaf(w, v.z, acc.z); acc.w = fmaf(w, v.w, acc.w);
            }
        }
        // combine the two edge groups
        acc.x += __shfl_xor_sync(0xffffffffu, acc.x, 16);
        acc.y += __shfl_xor_sync(0xffffffffu, acc.y, 16);
        acc.z += __shfl_xor_sync(0xffffffffu, acc.z, 16);
        acc.w += __shfl_xor_sync(0xffffffffu, acc.w, 16);

        if (lane < S4) {
            float4 a = g_alpha4[lane];
            float4 cm = __ldg(&colsum_in[lane]);
            outv.x = a.x * acc.x + (1.0f - a.x) * (cm.x * inv_n);
            outv.y = a.y * acc.y + (1.0f - a.y) * (cm.y * inv_n);
            outv.z = a.z * acc.z + (1.0f - a.z) * (cm.z * inv_n);
            outv.w = a.w * acc.w + (1.0f - a.w) * (cm.w * inv_n);
            if (g_known[i]) {
                float4 b = g_beta4[lane];
                float4 xk = __ldg(&g_xk[i * S4 + lane]);
                outv.x = b.x * outv.x + (1.0f - b.x) * xk.x;
                outv.y = b.y * outv.y + (1.0f - b.y) * xk.y;
                outv.z = b.z * outv.z + (1.0f - b.z) * xk.z;
                outv.w = b.w * outv.w + (1.0f - b.w) * xk.w;
            }
            if (!final_add_mean) {
                dst[i * S4 + lane] = outv;
            } else {
                float4 m = g_mean4[lane];
                outv.x += m.x; outv.y += m.y; outv.z += m.z; outv.w += m.w;
                float2* o2 = (float2*)(dout + i * DATTR);
                if (lane < 12) {
                    o2[2 * lane]     = make_float2(outv.x, outv.y);
                    o2[2 * lane + 1] = make_float2(outv.z, outv.w);
                } else if (lane == 12) {
                    o2[24] = make_float2(outv.x, outv.y);
                }
            }
        }
    }

    if (!final_add_mean) {
        __shared__ float sm[SPAD];
        if (threadIdx.x < SPAD) sm[threadIdx.x] = 0.0f;
        __syncthreads();
        if (valid && lane < S4) {
            atomicAdd(&sm[4 * lane],     outv.x);
            atomicAdd(&sm[4 * lane + 1], outv.y);
            atomicAdd(&sm[4 * lane + 2], outv.z);
            atomicAdd(&sm[4 * lane + 3], outv.w);
        }
        __syncthreads();
        if (threadIdx.x < DATTR)
            atomicAdd(&colsum_out[threadIdx.x], sm[threadIdx.x]);
    }
}

// ---------------------------------------------------------------------------

extern "C" void kernel_launch(void* const* d_in, const int* in_sizes, int n_in,
                              void* d_out, int out_size) {
    const float* x     = (const float*)d_in[0];
    const float* eta   = (const float*)d_in[1];
    const float* theta = (const float*)d_in[2];
    const int*   ei    = (const int*)d_in[3];
    const int*   mask  = (const int*)d_in[4];

    const int D = in_sizes[1];        // 50
    const int n = in_sizes[0] / D;    // 100000
    const int e = in_sizes[3] / 2;    // 1600000
    const int k = in_sizes[4];        // 50000
    const int* row = ei;
    const int* col = ei + e;

    float4 *bufA, *bufB, *colsum4;
    cudaGetSymbolAddress((void**)&bufA, g_bufA);
    cudaGetSymbolAddress((void**)&bufB, g_bufB);
    cudaGetSymbolAddress((void**)&colsum4, g_colsum4);

    int nb_scan = (n + SCANB - 1) / SCANB;    // 98

    zero_kernel<<<(n + 255) / 256, 256>>>(n);
    deg_kernel<<<(e + 255) / 256, 256>>>(row, e);
    dinv_alpha_kernel<<<(n + 255) / 256, 256>>>(eta, theta, n, D);
    scan_sum_kernel<<<nb_scan, SCANB>>>(n);
    scan_top_kernel<<<1, 128>>>(nb_scan, n);
    scan_write_kernel<<<nb_scan, SCANB>>>(n);
    scatter_kernel<<<(e + 255) / 256, 256>>>(row, col, e);
    mask_mean_kernel<<<64, 256>>>(x, mask, k);
    mean_div_kernel<<<1, 64>>>(k);

    int nblocks = (n + WPB - 1) / WPB;
    init_kernel<<<nblocks, 256>>>(x, n);

    float inv_n = 1.0f / (float)n;
    float4* bufs[2] = { bufA, bufB };
    for (int t = 0; t < NUM_ITER; t++) {
        const float4* src = bufs[t & 1];
        int is_final = (t == NUM_ITER - 1);
        float4* dst = bufs[(t + 1) & 1];
        spmm_kernel<<<nblocks, 256>>>(src, dst, (float*)d_out,
                                      colsum4 + t * S4,
                                      (float*)(colsum4 + (t + 1) * S4),
                                      n, inv_n, is_final);
    }
}